// round 4
// baseline (speedup 1.0000x reference)
#include <cuda_runtime.h>
#include <cuda_bf16.h>
#include <stdint.h>

#define NBATCH 32
#define SEQ    1024
#define DIM    128

// ---------------- scratch (static __device__, no allocations) ----------------
__device__ __nv_bfloat16 g_WT[DIM * DIM];                      // W^T  bf16 [n][k]
__device__ __nv_bfloat16 g_BThi[DIM * DIM];                    // B^T hi
__device__ __nv_bfloat16 g_BTlo[DIM * DIM];                    // B^T lo
__device__ float         g_NB[(size_t)NBATCH * SEQ * DIM];     // nodes@B fp32 [b][s][d]
__device__ __nv_bfloat16 g_NWT[(size_t)NBATCH * DIM * SEQ];    // (nodes@W)^T bf16 [b][d][s]

// ---------------- mma.sync m16n8k16 bf16 -> fp32 ----------------
__device__ __forceinline__ void mma16816(float c[4], const uint32_t a[4], const uint32_t b[2]) {
    asm volatile(
        "mma.sync.aligned.m16n8k16.row.col.f32.bf16.bf16.f32 "
        "{%0,%1,%2,%3}, {%4,%5,%6,%7}, {%8,%9}, {%0,%1,%2,%3};\n"
        : "+f"(c[0]), "+f"(c[1]), "+f"(c[2]), "+f"(c[3])
        : "r"(a[0]), "r"(a[1]), "r"(a[2]), "r"(a[3]), "r"(b[0]), "r"(b[1]));
}

__device__ __forceinline__ void cp_async16(void* smem_dst, const void* gmem_src) {
    uint32_t dst = (uint32_t)__cvta_generic_to_shared(smem_dst);
    asm volatile("cp.async.cg.shared.global [%0], [%1], 16;\n" :: "r"(dst), "l"(gmem_src));
}

// ---------------- kernel 0: split/transpose weights ----------------
__global__ void prep_weights_kernel(const float* __restrict__ W, const float* __restrict__ Bm) {
    int idx = blockIdx.x * blockDim.x + threadIdx.x;
    if (idx >= DIM * DIM) return;
    int k = idx >> 7;
    int n = idx & (DIM - 1);
    g_WT[n * DIM + k] = __float2bfloat16(W[idx]);
    float bv = Bm[idx];
    __nv_bfloat16 hi = __float2bfloat16(bv);
    g_BThi[n * DIM + k] = hi;
    g_BTlo[n * DIM + k] = __float2bfloat16(bv - __bfloat162float(hi));
}

// ---------------- kernel 1: NB = nodes@B (3-split, fp32 out), NW^T = (nodes@W)^T (bf16) ----
// grid: (8 s-tiles, 32 batches, 2) ; z==0 -> W path, z==1 -> B path. 256 threads.
__global__ __launch_bounds__(256, 2) void phase1_kernel(const float* __restrict__ nodes) {
    const int s_tile = blockIdx.x;
    const int b      = blockIdx.y;
    const int which  = blockIdx.z;   // 0: W -> g_NWT ; 1: B -> g_NB

    __shared__ __align__(16) unsigned char smem_raw[40960];
    __nv_bfloat16 (*sAhi)[40] = reinterpret_cast<__nv_bfloat16(*)[40]>(smem_raw);
    __nv_bfloat16 (*sAlo)[40] = reinterpret_cast<__nv_bfloat16(*)[40]>(smem_raw + 10240);
    __nv_bfloat16 (*sWhi)[40] = reinterpret_cast<__nv_bfloat16(*)[40]>(smem_raw + 20480);
    __nv_bfloat16 (*sWlo)[40] = reinterpret_cast<__nv_bfloat16(*)[40]>(smem_raw + 30720);

    const int t    = threadIdx.x;
    const int warp = t >> 5;
    const int lane = t & 31;
    const int grp  = lane >> 2;
    const int thr  = lane & 3;
    const int m_base = (warp >> 1) * 32;   // 4 warps along M (128)
    const int n_base = (warp & 1) * 64;    // 2 warps along N (128)

    float acc[2][8][4];
    #pragma unroll
    for (int mf = 0; mf < 2; mf++)
        #pragma unroll
        for (int f = 0; f < 8; f++)
            #pragma unroll
            for (int c = 0; c < 4; c++) acc[mf][f][c] = 0.f;

    const float* Abase = nodes + ((size_t)b * SEQ + s_tile * 128) * DIM;
    const __nv_bfloat16* wtHi = which ? g_BThi : g_WT;

    for (int kt = 0; kt < 4; kt++) {             // K=128 in 4 tiles of 32
        #pragma unroll
        for (int j = 0; j < 16; j++) {
            int idx = t + 256 * j;               // 128 rows x 32 cols
            int row = idx >> 5;
            int col = idx & 31;
            float x = Abase[row * DIM + kt * 32 + col];
            __nv_bfloat16 hi = __float2bfloat16(x);
            sAhi[row][col] = hi;
            sAlo[row][col] = __float2bfloat16(x - __bfloat162float(hi));
            sWhi[row][col] = wtHi[row * DIM + kt * 32 + col];
            if (which) sWlo[row][col] = g_BTlo[row * DIM + kt * 32 + col];
        }
        __syncthreads();
        #pragma unroll
        for (int ks = 0; ks < 32; ks += 16) {
            uint32_t a[2][4], al[2][4];
            #pragma unroll
            for (int mf = 0; mf < 2; mf++) {
                int m0 = m_base + mf * 16;
                a[mf][0] = *(const uint32_t*)&sAhi[m0 + grp    ][ks + thr * 2    ];
                a[mf][1] = *(const uint32_t*)&sAhi[m0 + grp + 8][ks + thr * 2    ];
                a[mf][2] = *(const uint32_t*)&sAhi[m0 + grp    ][ks + thr * 2 + 8];
                a[mf][3] = *(const uint32_t*)&sAhi[m0 + grp + 8][ks + thr * 2 + 8];
                if (which) {
                    al[mf][0] = *(const uint32_t*)&sAlo[m0 + grp    ][ks + thr * 2    ];
                    al[mf][1] = *(const uint32_t*)&sAlo[m0 + grp + 8][ks + thr * 2    ];
                    al[mf][2] = *(const uint32_t*)&sAlo[m0 + grp    ][ks + thr * 2 + 8];
                    al[mf][3] = *(const uint32_t*)&sAlo[m0 + grp + 8][ks + thr * 2 + 8];
                }
            }
            #pragma unroll
            for (int f = 0; f < 8; f++) {
                int n0 = n_base + f * 8 + grp;
                uint32_t bh[2];
                bh[0] = *(const uint32_t*)&sWhi[n0][ks + thr * 2    ];
                bh[1] = *(const uint32_t*)&sWhi[n0][ks + thr * 2 + 8];
                mma16816(acc[0][f], a[0], bh);
                mma16816(acc[1][f], a[1], bh);
                if (which) {
                    uint32_t bl[2];
                    bl[0] = *(const uint32_t*)&sWlo[n0][ks + thr * 2    ];
                    bl[1] = *(const uint32_t*)&sWlo[n0][ks + thr * 2 + 8];
                    mma16816(acc[0][f], a[0],  bl);
                    mma16816(acc[1][f], a[1],  bl);
                    mma16816(acc[0][f], al[0], bh);
                    mma16816(acc[1][f], al[1], bh);
                }
            }
        }
        __syncthreads();
    }

    if (which) {
        // NB fp32, natural layout, coalesced float2 stores
        float* outp = g_NB + ((size_t)b * SEQ + s_tile * 128) * DIM;
        #pragma unroll
        for (int mf = 0; mf < 2; mf++) {
            #pragma unroll
            for (int f = 0; f < 8; f++) {
                int r0 = m_base + mf * 16 + grp;
                int c  = n_base + f * 8 + thr * 2;
                *(float2*)&outp[ r0      * DIM + c] = make_float2(acc[mf][f][0], acc[mf][f][1]);
                *(float2*)&outp[(r0 + 8) * DIM + c] = make_float2(acc[mf][f][2], acc[mf][f][3]);
            }
        }
    } else {
        // NW -> bf16, transpose via smem, store [b][d][s] coalesced
        __nv_bfloat16 (*tb)[132] = reinterpret_cast<__nv_bfloat16(*)[132]>(smem_raw);
        #pragma unroll
        for (int mf = 0; mf < 2; mf++) {
            #pragma unroll
            for (int f = 0; f < 8; f++) {
                int r0 = m_base + mf * 16 + grp;
                int c  = n_base + f * 8 + thr * 2;
                uint32_t p01 = (uint32_t)__bfloat16_as_ushort(__float2bfloat16(acc[mf][f][0]))
                             | ((uint32_t)__bfloat16_as_ushort(__float2bfloat16(acc[mf][f][1])) << 16);
                uint32_t p23 = (uint32_t)__bfloat16_as_ushort(__float2bfloat16(acc[mf][f][2]))
                             | ((uint32_t)__bfloat16_as_ushort(__float2bfloat16(acc[mf][f][3])) << 16);
                *(uint32_t*)&tb[r0    ][c] = p01;
                *(uint32_t*)&tb[r0 + 8][c] = p23;
            }
        }
        __syncthreads();
        __nv_bfloat16* outp = g_NWT + (size_t)b * DIM * SEQ + s_tile * 128;
        #pragma unroll
        for (int j = 0; j < 64; j++) {
            int idx = t + 256 * j;     // [d][s] order, consecutive t -> consecutive s
            int d = idx >> 7;
            int s = idx & 127;
            outp[(size_t)d * SEQ + s] = tb[s][d];
        }
    }
}

// ---------------- kernel 2: S = mask^T @ NW, fragments built straight from raw adjacency ----
// grid: (8 i-tiles, 32 batches), 256 threads. out = lrelu(NB + S * inv(count))
// Raw int32 adjacency tile [o][i] double-buffered via cp.async; A-fragments converted
// in registers (conflict-free LDS.32); counts accumulated during conversion.
#define RAW_STRIDE 132   // 128 ints + 4 pad -> conflict-free fragment LDS

__global__ __launch_bounds__(256, 2) void phase2_kernel(const int* __restrict__ adj,
                                                        float* __restrict__ outp) {
    const int i_tile = blockIdx.x;
    const int b      = blockIdx.y;

    __shared__ __align__(16) int sRaw[2][64 * RAW_STRIDE];      // raw adjacency [o][i]
    __shared__ __align__(16) __nv_bfloat16 sV[2][128][72];      // NW^T tiles [d][o]
    __shared__ int   s_cnt[128];
    __shared__ float s_inv[128];

    const int t    = threadIdx.x;
    const int warp = t >> 5;
    const int lane = t & 31;
    const int grp  = lane >> 2;
    const int thr  = lane & 3;
    const int m_base = (warp >> 1) * 32;
    const int n_base = (warp & 1) * 64;

    if (t < 128) s_cnt[t] = 0;

    const int i0 = i_tile * 128;
    const int4* adjb = reinterpret_cast<const int4*>(adj + (size_t)b * SEQ * SEQ + i0);
    const __nv_bfloat16* vb = g_NWT + (size_t)b * DIM * SEQ;

    float acc[2][8][4];
    #pragma unroll
    for (int mf = 0; mf < 2; mf++)
        #pragma unroll
        for (int f = 0; f < 8; f++)
            #pragma unroll
            for (int c = 0; c < 4; c++) acc[mf][f][c] = 0.f;

    // per-thread degree counters for the 4 exclusive i-rows this thread converts
    int cnt[4] = {0, 0, 0, 0};
    const int row_of[4] = { m_base + grp, m_base + grp + 8,
                            m_base + 16 + grp, m_base + 24 + grp };

    // raw adjacency copy mapping: chunk c = t + 256j (j<8): o = c>>5, 16B-chunk (c&31)
    const int ro  = t >> 5;          // base o for j stepping by 8
    const int rc  = t & 31;          // 16B chunk within row
    // sV copy mapping: idx = t + 256j (j<4): d = idx>>3, 16B-chunk idx&7
    const int vd  = t >> 3;
    const int vc8 = t & 7;

    // ---- prologue: tile 0 into buffer 0 ----
    #pragma unroll
    for (int j = 0; j < 8; j++) {
        int o = ro + 8 * j;
        cp_async16(&sRaw[0][o * RAW_STRIDE + rc * 4], &adjb[(size_t)o * (SEQ / 4) + rc]);
    }
    #pragma unroll
    for (int j = 0; j < 4; j++) {
        int d = vd + 32 * j;
        cp_async16(&sV[0][d][vc8 * 8], vb + (size_t)d * SEQ + vc8 * 8);
    }
    asm volatile("cp.async.commit_group;\n" ::: "memory");

    for (int kt = 0; kt < 16; kt++) {           // K=1024 over 'out' nodes, tiles of 64
        const int buf = kt & 1;

        if (kt < 15) {
            const int o0n = (kt + 1) * 64;
            #pragma unroll
            for (int j = 0; j < 8; j++) {
                int o = ro + 8 * j;
                cp_async16(&sRaw[buf ^ 1][o * RAW_STRIDE + rc * 4],
                           &adjb[(size_t)(o0n + o) * (SEQ / 4) + rc]);
            }
            #pragma unroll
            for (int j = 0; j < 4; j++) {
                int d = vd + 32 * j;
                cp_async16(&sV[buf ^ 1][d][vc8 * 8], vb + (size_t)d * SEQ + o0n + vc8 * 8);
            }
            asm volatile("cp.async.commit_group;\n" ::: "memory");
            asm volatile("cp.async.wait_group 1;\n" ::: "memory");   // tile kt landed
        } else {
            asm volatile("cp.async.wait_group 0;\n" ::: "memory");
        }
        __syncthreads();

        const int* raw = sRaw[buf];
        #pragma unroll
        for (int ks = 0; ks < 64; ks += 16) {
            uint32_t a[2][4];
            #pragma unroll
            for (int mf = 0; mf < 2; mf++) {
                #pragma unroll
                for (int r = 0; r < 4; r++) {
                    const int i  = m_base + mf * 16 + grp + (r & 1) * 8;   // row_of[mf*2+(r&1)]
                    const int o  = ks + thr * 2 + (r >> 1) * 8;
                    const int v0 = raw[o * RAW_STRIDE + i];
                    const int v1 = raw[(o + 1) * RAW_STRIDE + i];
                    const int m0v = (v0 != 0);
                    const int m1v = (v1 != 0);
                    cnt[mf * 2 + (r & 1)] += m0v + m1v;
                    a[mf][r] = (m0v ? 0x3F80u : 0u) | (m1v ? 0x3F800000u : 0u);
                }
            }
            #pragma unroll
            for (int f = 0; f < 8; f++) {
                int n0 = n_base + f * 8 + grp;
                uint32_t bb[2];
                bb[0] = *(const uint32_t*)&sV[buf][n0][ks + thr * 2    ];
                bb[1] = *(const uint32_t*)&sV[buf][n0][ks + thr * 2 + 8];
                mma16816(acc[0][f], a[0], bb);
                mma16816(acc[1][f], a[1], bb);
            }
        }
        __syncthreads();
    }

    // reduce per-thread degree counts (each (i,o) counted once per M-group,
    // duplicated by the 2 N-warps -> totals are 2x true degree)
    #pragma unroll
    for (int e = 0; e < 4; e++) atomicAdd(&s_cnt[row_of[e]], cnt[e]);
    __syncthreads();
    if (t < 128) {
        int c2 = s_cnt[t];                         // = 2 * degree
        s_inv[t] = (c2 > 0) ? (2.0f / (float)c2) : 0.0f;   // exact: 2/(2c) == 1/c
    }
    __syncthreads();

    // epilogue: out = lrelu(NB + S * inv)
    const float* nb = g_NB + ((size_t)b * SEQ + i0) * DIM;
    float*       ob = outp + ((size_t)b * SEQ + i0) * DIM;
    #pragma unroll
    for (int mf = 0; mf < 2; mf++) {
        #pragma unroll
        for (int f = 0; f < 8; f++) {
            int r0 = m_base + mf * 16 + grp;
            int c  = n_base + f * 8 + thr * 2;
            {
                float inv = s_inv[r0];
                float2 nv = *(const float2*)&nb[r0 * DIM + c];
                float x0 = nv.x + acc[mf][f][0] * inv;
                float x1 = nv.y + acc[mf][f][1] * inv;
                x0 = (x0 > 0.f) ? x0 : 0.1f * x0;
                x1 = (x1 > 0.f) ? x1 : 0.1f * x1;
                *(float2*)&ob[r0 * DIM + c] = make_float2(x0, x1);
            }
            {
                float inv = s_inv[r0 + 8];
                float2 nv = *(const float2*)&nb[(r0 + 8) * DIM + c];
                float x0 = nv.x + acc[mf][f][2] * inv;
                float x1 = nv.y + acc[mf][f][3] * inv;
                x0 = (x0 > 0.f) ? x0 : 0.1f * x0;
                x1 = (x1 > 0.f) ? x1 : 0.1f * x1;
                *(float2*)&ob[(r0 + 8) * DIM + c] = make_float2(x0, x1);
            }
        }
    }
}

// ---------------- launch ----------------
extern "C" void kernel_launch(void* const* d_in, const int* in_sizes, int n_in,
                              void* d_out, int out_size) {
    const float* nodes    = (const float*)d_in[0];   // [32,1024,128] f32
    const int*   adjacent = (const int*)  d_in[1];   // [32,1024,1024] i32
    const float* W        = (const float*)d_in[2];   // [128,128] f32
    const float* Bm       = (const float*)d_in[3];   // [128,128] f32
    float*       out      = (float*)d_out;           // [32,1024,128] f32

    prep_weights_kernel<<<64, 256>>>(W, Bm);
    phase1_kernel<<<dim3(8, 32, 2), 256>>>(nodes);
    phase2_kernel<<<dim3(8, 32), 256>>>(adjacent, out);
}

// round 13
// speedup vs baseline: 1.0242x; 1.0242x over previous
#include <cuda_runtime.h>
#include <cuda_bf16.h>
#include <stdint.h>

#define NBATCH 32
#define SEQ    1024
#define DIM    128

// ---------------- scratch (static __device__, no allocations) ----------------
__device__ __nv_bfloat16 g_WT[DIM * DIM];                      // W^T  bf16 [n][k]
__device__ __nv_bfloat16 g_BThi[DIM * DIM];                    // B^T hi
__device__ __nv_bfloat16 g_BTlo[DIM * DIM];                    // B^T lo
__device__ float         g_NB[(size_t)NBATCH * SEQ * DIM];     // nodes@B fp32 [b][s][d]
__device__ __nv_bfloat16 g_NWT[(size_t)NBATCH * DIM * SEQ];    // (nodes@W)^T bf16 [b][d][s]

// ---------------- mma.sync m16n8k16 bf16 -> fp32 ----------------
__device__ __forceinline__ void mma16816(float c[4], const uint32_t a[4], const uint32_t b[2]) {
    asm volatile(
        "mma.sync.aligned.m16n8k16.row.col.f32.bf16.bf16.f32 "
        "{%0,%1,%2,%3}, {%4,%5,%6,%7}, {%8,%9}, {%0,%1,%2,%3};\n"
        : "+f"(c[0]), "+f"(c[1]), "+f"(c[2]), "+f"(c[3])
        : "r"(a[0]), "r"(a[1]), "r"(a[2]), "r"(a[3]), "r"(b[0]), "r"(b[1]));
}

__device__ __forceinline__ void cp_async16(void* smem_dst, const void* gmem_src) {
    uint32_t dst = (uint32_t)__cvta_generic_to_shared(smem_dst);
    asm volatile("cp.async.cg.shared.global [%0], [%1], 16;\n" :: "r"(dst), "l"(gmem_src));
}

__device__ __forceinline__ void ldsm_x4(uint32_t& r0, uint32_t& r1, uint32_t& r2, uint32_t& r3,
                                        uint32_t addr) {
    asm volatile("ldmatrix.sync.aligned.m8n8.x4.shared.b16 {%0,%1,%2,%3}, [%4];"
                 : "=r"(r0), "=r"(r1), "=r"(r2), "=r"(r3) : "r"(addr));
}

// ---------------- kernel 0: split/transpose weights (R4-measured config) ----------------
__global__ void prep_weights_kernel(const float* __restrict__ W, const float* __restrict__ Bm) {
    int idx = blockIdx.x * blockDim.x + threadIdx.x;
    if (idx >= DIM * DIM) return;
    int k = idx >> 7;
    int n = idx & (DIM - 1);
    g_WT[n * DIM + k] = __float2bfloat16(W[idx]);
    float bv = Bm[idx];
    __nv_bfloat16 hi = __float2bfloat16(bv);
    g_BThi[n * DIM + k] = hi;
    g_BTlo[n * DIM + k] = __float2bfloat16(bv - __bfloat162float(hi));
}

// ---------------- kernel 1: NB = nodes@B (3-split), NW^T = (nodes@W)^T (bf16) ----------------
// grid: (8 s-tiles, 32 batches, 2) ; z==0 -> W path, z==1 -> B path. 256 threads.
__global__ __launch_bounds__(256, 2) void phase1_kernel(const float* __restrict__ nodes) {
    const int s_tile = blockIdx.x;
    const int b      = blockIdx.y;
    const int which  = blockIdx.z;

    __shared__ __align__(16) unsigned char smem_raw[40960];
    __nv_bfloat16 (*sAhi)[40] = reinterpret_cast<__nv_bfloat16(*)[40]>(smem_raw);
    __nv_bfloat16 (*sAlo)[40] = reinterpret_cast<__nv_bfloat16(*)[40]>(smem_raw + 10240);
    __nv_bfloat16 (*sWhi)[40] = reinterpret_cast<__nv_bfloat16(*)[40]>(smem_raw + 20480);
    __nv_bfloat16 (*sWlo)[40] = reinterpret_cast<__nv_bfloat16(*)[40]>(smem_raw + 30720);

    const int t    = threadIdx.x;
    const int warp = t >> 5;
    const int lane = t & 31;
    const int grp  = lane >> 2;
    const int thr  = lane & 3;
    const int m_base = (warp >> 1) * 32;
    const int n_base = (warp & 1) * 64;

    float acc[2][8][4];
    #pragma unroll
    for (int mf = 0; mf < 2; mf++)
        #pragma unroll
        for (int f = 0; f < 8; f++)
            #pragma unroll
            for (int c = 0; c < 4; c++) acc[mf][f][c] = 0.f;

    const float* Abase = nodes + ((size_t)b * SEQ + s_tile * 128) * DIM;
    const __nv_bfloat16* wtHi = which ? g_BThi : g_WT;

    for (int kt = 0; kt < 4; kt++) {
        #pragma unroll
        for (int j = 0; j < 16; j++) {
            int idx = t + 256 * j;
            int row = idx >> 5;
            int col = idx & 31;
            float x = Abase[row * DIM + kt * 32 + col];
            __nv_bfloat16 hi = __float2bfloat16(x);
            sAhi[row][col] = hi;
            sWhi[row][col] = wtHi[row * DIM + kt * 32 + col];
            if (which) {
                sAlo[row][col] = __float2bfloat16(x - __bfloat162float(hi));   // lo-terms only
                sWlo[row][col] = g_BTlo[row * DIM + kt * 32 + col];            // used on B path
            }
        }
        __syncthreads();
        #pragma unroll
        for (int ks = 0; ks < 32; ks += 16) {
            uint32_t a[2][4], al[2][4];
            #pragma unroll
            for (int mf = 0; mf < 2; mf++) {
                int m0 = m_base + mf * 16;
                a[mf][0] = *(const uint32_t*)&sAhi[m0 + grp    ][ks + thr * 2    ];
                a[mf][1] = *(const uint32_t*)&sAhi[m0 + grp + 8][ks + thr * 2    ];
                a[mf][2] = *(const uint32_t*)&sAhi[m0 + grp    ][ks + thr * 2 + 8];
                a[mf][3] = *(const uint32_t*)&sAhi[m0 + grp + 8][ks + thr * 2 + 8];
                if (which) {
                    al[mf][0] = *(const uint32_t*)&sAlo[m0 + grp    ][ks + thr * 2    ];
                    al[mf][1] = *(const uint32_t*)&sAlo[m0 + grp + 8][ks + thr * 2    ];
                    al[mf][2] = *(const uint32_t*)&sAlo[m0 + grp    ][ks + thr * 2 + 8];
                    al[mf][3] = *(const uint32_t*)&sAlo[m0 + grp + 8][ks + thr * 2 + 8];
                }
            }
            #pragma unroll
            for (int f = 0; f < 8; f++) {
                int n0 = n_base + f * 8 + grp;
                uint32_t bh[2];
                bh[0] = *(const uint32_t*)&sWhi[n0][ks + thr * 2    ];
                bh[1] = *(const uint32_t*)&sWhi[n0][ks + thr * 2 + 8];
                mma16816(acc[0][f], a[0], bh);
                mma16816(acc[1][f], a[1], bh);
                if (which) {
                    uint32_t bl[2];
                    bl[0] = *(const uint32_t*)&sWlo[n0][ks + thr * 2    ];
                    bl[1] = *(const uint32_t*)&sWlo[n0][ks + thr * 2 + 8];
                    mma16816(acc[0][f], a[0],  bl);
                    mma16816(acc[1][f], a[1],  bl);
                    mma16816(acc[0][f], al[0], bh);
                    mma16816(acc[1][f], al[1], bh);
                }
            }
        }
        __syncthreads();
    }

    if (which) {
        float* outp = g_NB + ((size_t)b * SEQ + s_tile * 128) * DIM;
        #pragma unroll
        for (int mf = 0; mf < 2; mf++) {
            #pragma unroll
            for (int f = 0; f < 8; f++) {
                int r0 = m_base + mf * 16 + grp;
                int c  = n_base + f * 8 + thr * 2;
                *(float2*)&outp[ r0      * DIM + c] = make_float2(acc[mf][f][0], acc[mf][f][1]);
                *(float2*)&outp[(r0 + 8) * DIM + c] = make_float2(acc[mf][f][2], acc[mf][f][3]);
            }
        }
    } else {
        __nv_bfloat16 (*tb)[132] = reinterpret_cast<__nv_bfloat16(*)[132]>(smem_raw);
        #pragma unroll
        for (int mf = 0; mf < 2; mf++) {
            #pragma unroll
            for (int f = 0; f < 8; f++) {
                int r0 = m_base + mf * 16 + grp;
                int c  = n_base + f * 8 + thr * 2;
                uint32_t p01 = (uint32_t)__bfloat16_as_ushort(__float2bfloat16(acc[mf][f][0]))
                             | ((uint32_t)__bfloat16_as_ushort(__float2bfloat16(acc[mf][f][1])) << 16);
                uint32_t p23 = (uint32_t)__bfloat16_as_ushort(__float2bfloat16(acc[mf][f][2]))
                             | ((uint32_t)__bfloat16_as_ushort(__float2bfloat16(acc[mf][f][3])) << 16);
                *(uint32_t*)&tb[r0    ][c] = p01;
                *(uint32_t*)&tb[r0 + 8][c] = p23;
            }
        }
        __syncthreads();
        __nv_bfloat16* outp = g_NWT + (size_t)b * DIM * SEQ + s_tile * 128;
        #pragma unroll
        for (int j = 0; j < 64; j++) {
            int idx = t + 256 * j;
            int d = idx >> 7;
            int s = idx & 127;
            outp[(size_t)d * SEQ + s] = tb[s][d];
        }
    }
}

// ---------------- kernel 2: S = mask^T @ NW (raw adjacency smem + reg-convert + LDSM B) ----
// grid: (8 i-tiles, 32 batches), 256 threads. out = lrelu(NB + S * inv(count))
#define RAW_STRIDE 132   // 128 ints + 4 pad -> conflict-free fragment LDS

__global__ __launch_bounds__(256, 2) void phase2_kernel(const int* __restrict__ adj,
                                                        float* __restrict__ outp) {
    const int i_tile = blockIdx.x;
    const int b      = blockIdx.y;

    __shared__ __align__(16) int sRaw[2][64 * RAW_STRIDE];      // raw adjacency [o][i]
    __shared__ __align__(16) __nv_bfloat16 sV[2][128][72];      // NW^T tiles [d][o]
    __shared__ int   s_cnt[128];
    __shared__ float s_inv[128];

    const int t    = threadIdx.x;
    const int warp = t >> 5;
    const int lane = t & 31;
    const int grp  = lane >> 2;
    const int thr  = lane & 3;
    const int m_base = (warp >> 1) * 32;
    const int n_base = (warp & 1) * 64;

    if (t < 128) s_cnt[t] = 0;

    const int i0 = i_tile * 128;
    const int4* adjb = reinterpret_cast<const int4*>(adj + (size_t)b * SEQ * SEQ + i0);
    const __nv_bfloat16* vb = g_NWT + (size_t)b * DIM * SEQ;

    float acc[2][8][4];
    #pragma unroll
    for (int mf = 0; mf < 2; mf++)
        #pragma unroll
        for (int f = 0; f < 8; f++)
            #pragma unroll
            for (int c = 0; c < 4; c++) acc[mf][f][c] = 0.f;

    // per-thread degree counters for the 4 exclusive i-rows this thread converts
    int cnt[4] = {0, 0, 0, 0};
    const int row_of[4] = { m_base + grp, m_base + grp + 8,
                            m_base + 16 + grp, m_base + 24 + grp };

    const int ro  = t >> 5;          // base o for raw copy (steps of 8)
    const int rc  = t & 31;          // 16B chunk within row
    const int vd  = t >> 3;          // base d for sV copy (steps of 32)
    const int vc8 = t & 7;

    // LDSM B-fragment lane mapping (m8n8.x4, non-trans):
    //   row-in-matrix = lane&7, khalf = (lane>>3)&1, f-offset = (lane>>4)&1
    // matrix j covers f = {2j, 2j+1}; address = &sV[buf][n_base + (2j + fo)*8 + row][ks + khalf*8]
    const int lrow = lane & 7;
    const int lkh  = (lane >> 3) & 1;
    const int lfo  = (lane >> 4) & 1;
    const int brow = n_base + lfo * 8 + lrow;

    // ---- prologue: tile 0 into buffer 0 ----
    #pragma unroll
    for (int j = 0; j < 8; j++) {
        int o = ro + 8 * j;
        cp_async16(&sRaw[0][o * RAW_STRIDE + rc * 4], &adjb[(size_t)o * (SEQ / 4) + rc]);
    }
    #pragma unroll
    for (int j = 0; j < 4; j++) {
        int d = vd + 32 * j;
        cp_async16(&sV[0][d][vc8 * 8], vb + (size_t)d * SEQ + vc8 * 8);
    }
    asm volatile("cp.async.commit_group;\n" ::: "memory");

    for (int kt = 0; kt < 16; kt++) {           // K=1024 over 'out' nodes, tiles of 64
        const int buf = kt & 1;

        if (kt < 15) {
            const int o0n = (kt + 1) * 64;
            #pragma unroll
            for (int j = 0; j < 8; j++) {
                int o = ro + 8 * j;
                cp_async16(&sRaw[buf ^ 1][o * RAW_STRIDE + rc * 4],
                           &adjb[(size_t)(o0n + o) * (SEQ / 4) + rc]);
            }
            #pragma unroll
            for (int j = 0; j < 4; j++) {
                int d = vd + 32 * j;
                cp_async16(&sV[buf ^ 1][d][vc8 * 8], vb + (size_t)d * SEQ + o0n + vc8 * 8);
            }
            asm volatile("cp.async.commit_group;\n" ::: "memory");
            asm volatile("cp.async.wait_group 1;\n" ::: "memory");   // tile kt landed
        } else {
            asm volatile("cp.async.wait_group 0;\n" ::: "memory");
        }
        __syncthreads();

        const int* raw = sRaw[buf];
        const uint32_t bBase = (uint32_t)__cvta_generic_to_shared(&sV[buf][brow][lkh * 8]);
        #pragma unroll
        for (int ks = 0; ks < 64; ks += 16) {
            uint32_t a[2][4];
            #pragma unroll
            for (int mf = 0; mf < 2; mf++) {
                #pragma unroll
                for (int r = 0; r < 4; r++) {
                    const int i  = m_base + mf * 16 + grp + (r & 1) * 8;
                    const int o  = ks + thr * 2 + (r >> 1) * 8;
                    const int v0 = raw[o * RAW_STRIDE + i];
                    const int v1 = raw[(o + 1) * RAW_STRIDE + i];
                    const int m0v = (v0 != 0);
                    const int m1v = (v1 != 0);
                    cnt[mf * 2 + (r & 1)] += m0v + m1v;
                    a[mf][r] = (m0v ? 0x3F80u : 0u) | (m1v ? 0x3F800000u : 0u);
                }
            }
            #pragma unroll
            for (int j = 0; j < 4; j++) {
                uint32_t r0, r1, r2, r3;
                ldsm_x4(r0, r1, r2, r3, bBase + (uint32_t)(j * (16 * 144) + ks * 2));
                uint32_t b0[2] = { r0, r1 };      // f = 2j
                uint32_t b1[2] = { r2, r3 };      // f = 2j+1
                mma16816(acc[0][2 * j    ], a[0], b0);
                mma16816(acc[1][2 * j    ], a[1], b0);
                mma16816(acc[0][2 * j + 1], a[0], b1);
                mma16816(acc[1][2 * j + 1], a[1], b1);
            }
        }
        __syncthreads();
    }

    // reduce per-thread degree counts (each (i,o) counted once per M-group,
    // duplicated by the 2 N-warps -> totals are 2x true degree)
    #pragma unroll
    for (int e = 0; e < 4; e++) atomicAdd(&s_cnt[row_of[e]], cnt[e]);
    __syncthreads();
    if (t < 128) {
        int c2 = s_cnt[t];                         // = 2 * degree
        s_inv[t] = (c2 > 0) ? (2.0f / (float)c2) : 0.0f;   // exact: 2/(2c) == 1/c
    }
    __syncthreads();

    // epilogue: out = lrelu(NB + S * inv)
    const float* nb = g_NB + ((size_t)b * SEQ + i0) * DIM;
    float*       ob = outp + ((size_t)b * SEQ + i0) * DIM;
    #pragma unroll
    for (int mf = 0; mf < 2; mf++) {
        #pragma unroll
        for (int f = 0; f < 8; f++) {
            int r0 = m_base + mf * 16 + grp;
            int c  = n_base + f * 8 + thr * 2;
            {
                float inv = s_inv[r0];
                float2 nv = *(const float2*)&nb[r0 * DIM + c];
                float x0 = nv.x + acc[mf][f][0] * inv;
                float x1 = nv.y + acc[mf][f][1] * inv;
                x0 = (x0 > 0.f) ? x0 : 0.1f * x0;
                x1 = (x1 > 0.f) ? x1 : 0.1f * x1;
                *(float2*)&ob[r0 * DIM + c] = make_float2(x0, x1);
            }
            {
                float inv = s_inv[r0 + 8];
                float2 nv = *(const float2*)&nb[(r0 + 8) * DIM + c];
                float x0 = nv.x + acc[mf][f][2] * inv;
                float x1 = nv.y + acc[mf][f][3] * inv;
                x0 = (x0 > 0.f) ? x0 : 0.1f * x0;
                x1 = (x1 > 0.f) ? x1 : 0.1f * x1;
                *(float2*)&ob[(r0 + 8) * DIM + c] = make_float2(x0, x1);
            }
        }
    }
}

// ---------------- launch ----------------
extern "C" void kernel_launch(void* const* d_in, const int* in_sizes, int n_in,
                              void* d_out, int out_size) {
    const float* nodes    = (const float*)d_in[0];   // [32,1024,128] f32
    const int*   adjacent = (const int*)  d_in[1];   // [32,1024,1024] i32
    const float* W        = (const float*)d_in[2];   // [128,128] f32
    const float* Bm       = (const float*)d_in[3];   // [128,128] f32
    float*       out      = (float*)d_out;           // [32,1024,128] f32

    prep_weights_kernel<<<64, 256>>>(W, Bm);
    phase1_kernel<<<dim3(8, 32, 2), 256>>>(nodes);
    phase2_kernel<<<dim3(8, 32), 256>>>(adjacent, out);
}